// round 6
// baseline (speedup 1.0000x reference)
#include <cuda_runtime.h>
#include <math_constants.h>

// Tiny transformer fully fused into ONE kernel, ONE block of 480 threads.
// CONTEXT=5, DIM=32, HEADS=4 (hd=8), NTOK=13, LAYERS=4.
//
// 3 warp-aligned groups of 160 threads:
//   A (0..159):   Q (kept in REGISTERS); scores+softmax+Ycat+Yproj. regs: Wq+Wp
//   B (160..319): K and V matmuls; final unembed.                   regs: Wk+Wv->Wu
//   C (320..479): H=relu(.@W1), Y=.@W2, residual X update.          regs: W1+W2
// Next layer's weights are prefetched into registers right after last use.
//
// Barriers per layer: bar1 = A+B (named, 320) after K/V, bar2 = A+C (named,
// 320) after Yproj, __syncthreads (480) after the X update. Row-wise matmuls
// are chained inside a warp via __shfl broadcasts; softmax (5-wide, tiny
// scores -> no max subtraction needed) is computed inline per lane.
// tokemb is staged to smem at entry so the tok->embedding gather is
// (parallel loads + LDS) instead of two chained global round-trips.

#define CTX    5
#define DIM    32
#define NTOK   13
#define HEADS  4
#define HD     8
#define LAYERS 4
#define SCALE  0.17677669529663687f   // 1/sqrt(32)
#define FULL   0xFFFFFFFFu

__global__ __launch_bounds__(480, 1)
void transformer_fused_kernel(
    const int*   __restrict__ toks,
    const float* __restrict__ pos,
    const float* __restrict__ tokemb,
    const float* __restrict__ gWq,
    const float* __restrict__ gWk,
    const float* __restrict__ gWv,
    const float* __restrict__ gWp,
    const float* __restrict__ gbp,
    const float* __restrict__ gW1,
    const float* __restrict__ gb1,
    const float* __restrict__ gW2,
    const float* __restrict__ gb2,
    const float* __restrict__ gWu,
    const float* __restrict__ gbu,
    float*       __restrict__ out)
{
    __shared__ __align__(16) float Xs [CTX * DIM];
    __shared__ __align__(16) float Ks [CTX * DIM];
    __shared__ __align__(16) float Vs [CTX * DIM];
    __shared__ __align__(16) float Yps[CTX * DIM];
    __shared__ __align__(16) float temb[NTOK * DIM];   // 416 floats
    __shared__ int toks_s[CTX];

    const int tid = threadIdx.x;
    const int g   = tid / 160;        // 0=A, 1=B, 2=C (warp-aligned)
    const int r   = tid - g * 160;    // 0..159
    const int c   = r >> 5;           // context row (warp-uniform)
    const int d   = r & 31;           // feature column (lane)

    float w0[DIM];    // A: Wq   B: Wk        C: W1
    float w1r[DIM];   // A: Wp   B: Wv -> Wu  C: W2
    float b0 = 0.f;   // A: bp   B: bu(end)   C: b1
    float b1v = 0.f;  //                      C: b2

    // ---- Entry: stage toks + tokemb, load pos, prefetch layer-0 weights ----
    if (tid < CTX) toks_s[tid] = toks[tid];
    if (g == 2 && r < (NTOK * DIM / 4))
        ((float4*)temb)[r] = ((const float4*)tokemb)[r];
    const float posv = (tid < 320) ? pos[r] : 0.f;

    if (g == 0) {
        #pragma unroll
        for (int i = 0; i < DIM; ++i) {
            w0[i]  = gWq[i * DIM + d];
            w1r[i] = gWp[i * DIM + d];
        }
        b0 = gbp[d];
    } else if (g == 1) {
        #pragma unroll
        for (int i = 0; i < DIM; ++i) {
            w0[i]  = gWk[i * DIM + d];
            w1r[i] = gWv[i * DIM + d];
        }
    } else {
        #pragma unroll
        for (int i = 0; i < DIM; ++i) {
            w0[i]  = gW1[i * DIM + d];
            w1r[i] = gW2[i * DIM + d];
        }
        b0  = gb1[d];
        b1v = gb2[d];
    }
    __syncthreads();

    #pragma unroll 1
    for (int l = 0; l < LAYERS; ++l) {
        const int ln = l + 1;
        float qreg = 0.f;    // A's Q[c][d], register-resident across phases

        // ===== Phase 1: A -> Q (regs); B -> K,V (smem); shfl matmuls =====
        if (g == 0) {
            const float xd = (l == 0) ? temb[toks_s[c] * DIM + d] + posv
                                      : Xs[r];
            if (l == 0) Xs[r] = xd;      // keep X for the residual path
            float a0 = 0.f, a1 = 0.f, a2 = 0.f, a3 = 0.f;
            #pragma unroll
            for (int i = 0; i < DIM; i += 4) {
                a0 = fmaf(__shfl_sync(FULL, xd, i    ), w0[i    ], a0);
                a1 = fmaf(__shfl_sync(FULL, xd, i + 1), w0[i + 1], a1);
                a2 = fmaf(__shfl_sync(FULL, xd, i + 2), w0[i + 2], a2);
                a3 = fmaf(__shfl_sync(FULL, xd, i + 3), w0[i + 3], a3);
            }
            qreg = (a0 + a1) + (a2 + a3);
            if (l < LAYERS - 1) {
                #pragma unroll
                for (int i = 0; i < DIM; ++i)
                    w0[i] = gWq[ln * DIM * DIM + i * DIM + d];
            }
            asm volatile("bar.sync 1, 320;" ::: "memory");
        } else if (g == 1) {
            const float xd = (l == 0) ? temb[toks_s[c] * DIM + d] + posv
                                      : Xs[r];
            float k0 = 0.f, k1 = 0.f, v0 = 0.f, v1 = 0.f;
            #pragma unroll
            for (int i = 0; i < DIM; i += 2) {
                const float xi = __shfl_sync(FULL, xd, i);
                const float xj = __shfl_sync(FULL, xd, i + 1);
                k0 = fmaf(xi, w0[i],      k0);
                k1 = fmaf(xj, w0[i + 1],  k1);
                v0 = fmaf(xi, w1r[i],     v0);
                v1 = fmaf(xj, w1r[i + 1], v1);
            }
            Ks[r] = k0 + k1;
            Vs[r] = v0 + v1;
            if (l < LAYERS - 1) {
                #pragma unroll
                for (int i = 0; i < DIM; ++i) {
                    w0[i]  = gWk[ln * DIM * DIM + i * DIM + d];
                    w1r[i] = gWv[ln * DIM * DIM + i * DIM + d];
                }
            } else if (r < CTX * NTOK) {   // last layer: Wu + bu for epilogue
                const int t = r % NTOK;
                #pragma unroll
                for (int i = 0; i < DIM; ++i)
                    w1r[i] = gWu[i * NTOK + t];
                b0 = gbu[t];
            }
            asm volatile("bar.sync 1, 320;" ::: "memory");
        }

        // ===== Phase 2 (A): scores+softmax+Ycat inline, Yproj via shfl =====
        if (g == 0) {
            const int h    = d >> 3;
            const int base = h * HD;
            float q[HD];
            #pragma unroll
            for (int i = 0; i < HD; ++i)
                q[i] = __shfl_sync(FULL, qreg, base + i);

            float e[CTX];
            #pragma unroll
            for (int k = 0; k < CTX; ++k) {
                if (k <= c) {
                    const float4 ka = *(const float4*)(Ks + k * DIM + base);
                    const float4 kb = *(const float4*)(Ks + k * DIM + base + 4);
                    float s0 = q[0] * ka.x + q[2] * ka.z;
                    float s1 = q[1] * ka.y + q[3] * ka.w;
                    s0 += q[4] * kb.x + q[6] * kb.z;
                    s1 += q[5] * kb.y + q[7] * kb.w;
                    e[k] = __expf((s0 + s1) * SCALE);
                } else {
                    e[k] = 0.f;
                }
            }
            const float inv =
                __fdividef(1.f, (e[0] + e[1]) + (e[2] + e[3]) + e[4]);
            float y = e[0] * Vs[0 * DIM + d];
            y = fmaf(e[1], Vs[1 * DIM + d], y);
            y = fmaf(e[2], Vs[2 * DIM + d], y);
            y = fmaf(e[3], Vs[3 * DIM + d], y);
            y = fmaf(e[4], Vs[4 * DIM + d], y);
            y *= inv;                                  // Ycat[c][d]

            // Yproj = Ycat @ Wp + bp (warp shuffle broadcast)
            float p0 = b0, p1 = 0.f, p2 = 0.f, p3 = 0.f;
            #pragma unroll
            for (int i = 0; i < DIM; i += 4) {
                p0 = fmaf(__shfl_sync(FULL, y, i    ), w1r[i    ], p0);
                p1 = fmaf(__shfl_sync(FULL, y, i + 1), w1r[i + 1], p1);
                p2 = fmaf(__shfl_sync(FULL, y, i + 2), w1r[i + 2], p2);
                p3 = fmaf(__shfl_sync(FULL, y, i + 3), w1r[i + 3], p3);
            }
            Yps[r] = (p0 + p1) + (p2 + p3);
            if (l < LAYERS - 1) {
                #pragma unroll
                for (int i = 0; i < DIM; ++i)
                    w1r[i] = gWp[ln * DIM * DIM + i * DIM + d];
                b0 = gbp[ln * DIM + d];
            }
            asm volatile("bar.sync 2, 320;" ::: "memory");
        }

        // ===== Phase 3 (C): H=relu(Yp@W1+b1); Y=H@W2+b2; X update =====
        if (g == 2) {
            asm volatile("bar.sync 2, 320;" ::: "memory");  // wait for Yps
            const float4* xr = (const float4*)(Yps + c * DIM);
            float a0 = b0, a1 = 0.f, a2 = 0.f, a3 = 0.f;
            #pragma unroll
            for (int i = 0; i < 8; ++i) {
                const float4 x = xr[i];
                a0 = fmaf(x.x, w0[4 * i    ], a0);
                a1 = fmaf(x.y, w0[4 * i + 1], a1);
                a2 = fmaf(x.z, w0[4 * i + 2], a2);
                a3 = fmaf(x.w, w0[4 * i + 3], a3);
            }
            const float hval = fmaxf((a0 + a1) + (a2 + a3), 0.f);

            float y0 = b1v, y1 = 0.f, y2 = 0.f, y3 = 0.f;
            #pragma unroll
            for (int i = 0; i < DIM; i += 4) {
                y0 = fmaf(__shfl_sync(FULL, hval, i    ), w1r[i    ], y0);
                y1 = fmaf(__shfl_sync(FULL, hval, i + 1), w1r[i + 1], y1);
                y2 = fmaf(__shfl_sync(FULL, hval, i + 2), w1r[i + 2], y2);
                y3 = fmaf(__shfl_sync(FULL, hval, i + 3), w1r[i + 3], y3);
            }
            // sole reader+writer of Xs[r] in this phase: no hazard
            Xs[r] += ((y0 + y1) + (y2 + y3)) + Yps[r];
            if (l < LAYERS - 1) {
                #pragma unroll
                for (int i = 0; i < DIM; ++i) {
                    w0[i]  = gW1[ln * DIM * DIM + i * DIM + d];
                    w1r[i] = gW2[ln * DIM * DIM + i * DIM + d];
                }
                b0  = gb1[ln * DIM + d];
                b1v = gb2[ln * DIM + d];
            }
        }
        __syncthreads();
    }

    // ---- Epilogue (B, Wu already in regs): out = X @ Wu + bu ----
    if (g == 1 && r < CTX * NTOK) {
        const int cc = r / NTOK;
        const float4* xr = (const float4*)(Xs + cc * DIM);
        float y0 = b0, y1 = 0.f, y2 = 0.f, y3 = 0.f;
        #pragma unroll
        for (int i = 0; i < 8; ++i) {
            const float4 x = xr[i];
            y0 = fmaf(x.x, w1r[4 * i    ], y0);
            y1 = fmaf(x.y, w1r[4 * i + 1], y1);
            y2 = fmaf(x.z, w1r[4 * i + 2], y2);
            y3 = fmaf(x.w, w1r[4 * i + 3], y3);
        }
        out[r] = (y0 + y1) + (y2 + y3);
    }
}

extern "C" void kernel_launch(void* const* d_in, const int* in_sizes, int n_in,
                              void* d_out, int out_size) {
    (void)in_sizes; (void)n_in; (void)out_size;
    const int*   toks   = (const int*)  d_in[0];
    const float* pos    = (const float*)d_in[1];
    const float* tokemb = (const float*)d_in[2];
    const float* Wq     = (const float*)d_in[3];
    const float* Wk     = (const float*)d_in[4];
    const float* Wv     = (const float*)d_in[5];
    const float* Wp     = (const float*)d_in[6];
    const float* bp     = (const float*)d_in[7];
    const float* W1     = (const float*)d_in[8];
    const float* b1     = (const float*)d_in[9];
    const float* W2     = (const float*)d_in[10];
    const float* b2     = (const float*)d_in[11];
    const float* Wu     = (const float*)d_in[12];
    const float* bu     = (const float*)d_in[13];
    float* out = (float*)d_out;

    transformer_fused_kernel<<<1, 480>>>(toks, pos, tokemb, Wq, Wk, Wv, Wp, bp,
                                         W1, b1, W2, b2, Wu, bu, out);
}

// round 7
// speedup vs baseline: 1.1545x; 1.1545x over previous
#include <cuda_runtime.h>
#include <math_constants.h>

// Tiny transformer fully fused into ONE kernel, ONE block of 480 threads.
// CONTEXT=5, DIM=32, HEADS=4 (hd=8), NTOK=13, LAYERS=4.
//
// 3 warp-aligned groups of 160 threads:
//   A (0..159):   Q matmul; scores+softmax+Ycat+Yproj.  regs: Wq + Wp
//   B (160..319): K,V matmuls; final unembed.           regs: Wk + Wv->Wu
//   C (320..479): H=relu(.@W1), Y=.@W2, X residual.     regs: W1 + W2
//
// Producer-arrive / consumer-sync named barriers keep weight-prefetch issue
// OFF every barrier's critical path:
//   bar1 (320): B arrives after K,V stores; A syncs.      (then B prefetches)
//   bar2 (320): A arrives after Yps store; C syncs.       (then A prefetches)
//   bar0 (480): C arrives after the X update; A+B sync at loop top.
// Row-wise matmuls chain inside a warp via __shfl broadcasts; softmax
// (5-wide, tiny scores -> max subtraction unnecessary) is inline per lane.

#define CTX    5
#define DIM    32
#define NTOK   13
#define HEADS  4
#define HD     8
#define LAYERS 4
#define SCALE  0.17677669529663687f   // 1/sqrt(32)
#define FULL   0xFFFFFFFFu

#define BAR_SYNC(id, n)   asm volatile("bar.sync %0, %1;"   :: "n"(id), "n"(n) : "memory")
#define BAR_ARRIVE(id, n) asm volatile("bar.arrive %0, %1;" :: "n"(id), "n"(n) : "memory")

__global__ __launch_bounds__(480, 1)
void transformer_fused_kernel(
    const int*   __restrict__ toks,
    const float* __restrict__ pos,
    const float* __restrict__ tokemb,
    const float* __restrict__ gWq,
    const float* __restrict__ gWk,
    const float* __restrict__ gWv,
    const float* __restrict__ gWp,
    const float* __restrict__ gbp,
    const float* __restrict__ gW1,
    const float* __restrict__ gb1,
    const float* __restrict__ gW2,
    const float* __restrict__ gb2,
    const float* __restrict__ gWu,
    const float* __restrict__ gbu,
    float*       __restrict__ out)
{
    __shared__ __align__(16) float Xs [CTX * DIM];
    __shared__ __align__(16) float Qs [CTX * DIM];
    __shared__ __align__(16) float Ks [CTX * DIM];
    __shared__ __align__(16) float Vs [CTX * DIM];
    __shared__ __align__(16) float Yps[CTX * DIM];

    const int tid = threadIdx.x;
    const int g   = tid / 160;        // 0=A, 1=B, 2=C (warp-aligned)
    const int r   = tid - g * 160;    // 0..159
    const int c   = r >> 5;           // context row (warp-uniform)
    const int d   = r & 31;           // feature column (lane)

    float w0[DIM];    // A: Wq   B: Wk        C: W1
    float w1r[DIM];   // A: Wp   B: Wv -> Wu  C: W2
    float b0 = 0.f;   // A: bp   B: bu(end)   C: b1
    float b1v = 0.f;  //                      C: b2

    // ---- Prologue: layer-0 weight prefetch + embedding (overlapped) ----
    if (g == 0) {
        #pragma unroll
        for (int i = 0; i < DIM; ++i) {
            w0[i]  = gWq[i * DIM + d];
            w1r[i] = gWp[i * DIM + d];
        }
        b0 = gbp[d];
        Xs[r] = tokemb[toks[c] * DIM + d] + pos[r];   // embedding
    } else if (g == 1) {
        #pragma unroll
        for (int i = 0; i < DIM; ++i) {
            w0[i]  = gWk[i * DIM + d];
            w1r[i] = gWv[i * DIM + d];
        }
    } else {
        #pragma unroll
        for (int i = 0; i < DIM; ++i) {
            w0[i]  = gW1[i * DIM + d];
            w1r[i] = gW2[i * DIM + d];
        }
        b0  = gb1[d];
        b1v = gb2[d];
    }
    __syncthreads();

    #pragma unroll 1
    for (int l = 0; l < LAYERS; ++l) {
        const int ln = l + 1;

        if (g == 0) {
            // ===== Phase 1 (A): Q = X @ Wq -> Qs =====
            if (l > 0) BAR_SYNC(0, 480);           // wait for X(l)
            {
                const float4* xr = (const float4*)(Xs + c * DIM);
                float a0 = 0.f, a1 = 0.f, a2 = 0.f, a3 = 0.f;
                #pragma unroll
                for (int i = 0; i < 8; ++i) {
                    const float4 x = xr[i];
                    a0 = fmaf(x.x, w0[4 * i    ], a0);
                    a1 = fmaf(x.y, w0[4 * i + 1], a1);
                    a2 = fmaf(x.z, w0[4 * i + 2], a2);
                    a3 = fmaf(x.w, w0[4 * i + 3], a3);
                }
                Qs[r] = (a0 + a1) + (a2 + a3);
            }
            if (l < LAYERS - 1) {                  // hidden in wait-for-B slack
                #pragma unroll
                for (int i = 0; i < DIM; ++i)
                    w0[i] = gWq[ln * DIM * DIM + i * DIM + d];
            }
            BAR_SYNC(1, 320);                      // wait for K,V

            // ===== Phase 2 (A): attention inline + Yproj via shfl =====
            {
                const int h    = d >> 3;
                const int base = h * HD;
                const float4 qa = *(const float4*)(Qs + c * DIM + base);
                const float4 qb = *(const float4*)(Qs + c * DIM + base + 4);
                float e[CTX];
                #pragma unroll
                for (int k = 0; k < CTX; ++k) {
                    if (k <= c) {
                        const float4 ka = *(const float4*)(Ks + k * DIM + base);
                        const float4 kb = *(const float4*)(Ks + k * DIM + base + 4);
                        float s0 = qa.x * ka.x + qa.z * ka.z;
                        float s1 = qa.y * ka.y + qa.w * ka.w;
                        s0 += qb.x * kb.x + qb.z * kb.z;
                        s1 += qb.y * kb.y + qb.w * kb.w;
                        e[k] = __expf((s0 + s1) * SCALE);
                    } else {
                        e[k] = 0.f;
                    }
                }
                const float inv =
                    __fdividef(1.f, (e[0] + e[1]) + (e[2] + e[3]) + e[4]);
                float y = e[0] * Vs[0 * DIM + d];
                y = fmaf(e[1], Vs[1 * DIM + d], y);
                y = fmaf(e[2], Vs[2 * DIM + d], y);
                y = fmaf(e[3], Vs[3 * DIM + d], y);
                y = fmaf(e[4], Vs[4 * DIM + d], y);
                y *= inv;                               // Ycat[c][d]

                float p0 = b0, p1 = 0.f, p2 = 0.f, p3 = 0.f;
                #pragma unroll
                for (int i = 0; i < DIM; i += 4) {
                    p0 = fmaf(__shfl_sync(FULL, y, i    ), w1r[i    ], p0);
                    p1 = fmaf(__shfl_sync(FULL, y, i + 1), w1r[i + 1], p1);
                    p2 = fmaf(__shfl_sync(FULL, y, i + 2), w1r[i + 2], p2);
                    p3 = fmaf(__shfl_sync(FULL, y, i + 3), w1r[i + 3], p3);
                }
                Yps[r] = (p0 + p1) + (p2 + p3);
            }
            BAR_ARRIVE(2, 320);                    // release C immediately
            if (l < LAYERS - 1) {                  // prefetch OFF critical path
                #pragma unroll
                for (int i = 0; i < DIM; ++i)
                    w1r[i] = gWp[ln * DIM * DIM + i * DIM + d];
                b0 = gbp[ln * DIM + d];
            }
        } else if (g == 1) {
            // ===== Phase 1 (B): K,V = X @ {Wk,Wv} -> Ks,Vs =====
            if (l > 0) BAR_SYNC(0, 480);           // wait for X(l)
            {
                const float4* xr = (const float4*)(Xs + c * DIM);
                float k0 = 0.f, k1 = 0.f, k2 = 0.f, k3 = 0.f;
                float v0 = 0.f, v1 = 0.f, v2 = 0.f, v3 = 0.f;
                #pragma unroll
                for (int i = 0; i < 8; ++i) {
                    const float4 x = xr[i];
                    k0 = fmaf(x.x, w0[4 * i    ], k0);
                    k1 = fmaf(x.y, w0[4 * i + 1], k1);
                    k2 = fmaf(x.z, w0[4 * i + 2], k2);
                    k3 = fmaf(x.w, w0[4 * i + 3], k3);
                    v0 = fmaf(x.x, w1r[4 * i    ], v0);
                    v1 = fmaf(x.y, w1r[4 * i + 1], v1);
                    v2 = fmaf(x.z, w1r[4 * i + 2], v2);
                    v3 = fmaf(x.w, w1r[4 * i + 3], v3);
                }
                Ks[r] = (k0 + k1) + (k2 + k3);
                Vs[r] = (v0 + v1) + (v2 + v3);
            }
            BAR_ARRIVE(1, 320);                    // release A immediately
            if (l < LAYERS - 1) {                  // prefetch OFF critical path
                #pragma unroll
                for (int i = 0; i < DIM; ++i) {
                    w0[i]  = gWk[ln * DIM * DIM + i * DIM + d];
                    w1r[i] = gWv[ln * DIM * DIM + i * DIM + d];
                }
            } else if (r < CTX * NTOK) {           // last layer: Wu + bu
                const int t = r % NTOK;
                #pragma unroll
                for (int i = 0; i < DIM; ++i)
                    w1r[i] = gWu[i * NTOK + t];
                b0 = gbu[t];
            }
        } else {
            // ===== Phase 3 (C): H=relu(Yp@W1+b1); Y=H@W2+b2; X update =====
            BAR_SYNC(2, 320);                      // wait for Yps
            {
                const float4* xr = (const float4*)(Yps + c * DIM);
                float a0 = b0, a1 = 0.f, a2 = 0.f, a3 = 0.f;
                #pragma unroll
                for (int i = 0; i < 8; ++i) {
                    const float4 x = xr[i];
                    a0 = fmaf(x.x, w0[4 * i    ], a0);
                    a1 = fmaf(x.y, w0[4 * i + 1], a1);
                    a2 = fmaf(x.z, w0[4 * i + 2], a2);
                    a3 = fmaf(x.w, w0[4 * i + 3], a3);
                }
                const float hval = fmaxf((a0 + a1) + (a2 + a3), 0.f);

                float y0 = b1v, y1 = 0.f, y2 = 0.f, y3 = 0.f;
                #pragma unroll
                for (int i = 0; i < DIM; i += 4) {
                    y0 = fmaf(__shfl_sync(FULL, hval, i    ), w1r[i    ], y0);
                    y1 = fmaf(__shfl_sync(FULL, hval, i + 1), w1r[i + 1], y1);
                    y2 = fmaf(__shfl_sync(FULL, hval, i + 2), w1r[i + 2], y2);
                    y3 = fmaf(__shfl_sync(FULL, hval, i + 3), w1r[i + 3], y3);
                }
                // sole reader+writer of Xs[r] here: no hazard
                Xs[r] += ((y0 + y1) + (y2 + y3)) + Yps[r];
            }
            BAR_ARRIVE(0, 480);                    // release A,B immediately
            if (l < LAYERS - 1) {                  // prefetch OFF critical path
                #pragma unroll
                for (int i = 0; i < DIM; ++i) {
                    w0[i]  = gW1[ln * DIM * DIM + i * DIM + d];
                    w1r[i] = gW2[ln * DIM * DIM + i * DIM + d];
                }
                b0  = gb1[ln * DIM + d];
                b1v = gb2[ln * DIM + d];
            }
        }
    }

    // ---- Final X barrier, then epilogue (B, Wu in regs) ----
    if (g < 2) {
        BAR_SYNC(0, 480);
        if (g == 1 && r < CTX * NTOK) {
            const int cc = r / NTOK;
            const float4* xr = (const float4*)(Xs + cc * DIM);
            float y0 = b0, y1 = 0.f, y2 = 0.f, y3 = 0.f;
            #pragma unroll
            for (int i = 0; i < 8; ++i) {
                const float4 x = xr[i];
                y0 = fmaf(x.x, w1r[4 * i    ], y0);
                y1 = fmaf(x.y, w1r[4 * i + 1], y1);
                y2 = fmaf(x.z, w1r[4 * i + 2], y2);
                y3 = fmaf(x.w, w1r[4 * i + 3], y3);
            }
            out[r] = (y0 + y1) + (y2 + y3);
        }
    }
}

extern "C" void kernel_launch(void* const* d_in, const int* in_sizes, int n_in,
                              void* d_out, int out_size) {
    (void)in_sizes; (void)n_in; (void)out_size;
    const int*   toks   = (const int*)  d_in[0];
    const float* pos    = (const float*)d_in[1];
    const float* tokemb = (const float*)d_in[2];
    const float* Wq     = (const float*)d_in[3];
    const float* Wk     = (const float*)d_in[4];
    const float* Wv     = (const float*)d_in[5];
    const float* Wp     = (const float*)d_in[6];
    const float* bp     = (const float*)d_in[7];
    const float* W1     = (const float*)d_in[8];
    const float* b1     = (const float*)d_in[9];
    const float* W2     = (const float*)d_in[10];
    const float* b2     = (const float*)d_in[11];
    const float* Wu     = (const float*)d_in[12];
    const float* bu     = (const float*)d_in[13];
    float* out = (float*)d_out;

    transformer_fused_kernel<<<1, 480>>>(toks, pos, tokemb, Wq, Wk, Wv, Wp, bp,
                                         W1, b1, W2, b2, Wu, bu, out);
}

// round 8
// speedup vs baseline: 1.1892x; 1.0300x over previous
#include <cuda_runtime.h>
#include <math_constants.h>

// Tiny transformer fully fused into ONE kernel, ONE block of 480 threads.
// CONTEXT=5, DIM=32, HEADS=4 (hd=8), NTOK=13, LAYERS=4.
//
// 3 warp-aligned groups of 160 threads:
//   A (0..159):   Q matmul; scores+softmax+Ycat+Yproj.  regs: Wq + Wp
//   B (160..319): K,V matmuls; final unembed.           regs: Wk + Wv->Wu
//   C (320..479): H=relu(.@W1), Y=.@W2, X residual.     regs: W1 + W2
//
// Producer-arrive / consumer-sync named barriers keep weight-prefetch issue
// OFF every barrier's critical path:
//   bar1 (320): B arrives after K,V stores; A syncs.      (then B prefetches)
//   bar2 (320): A arrives after Yps store; C syncs.       (then A prefetches)
//   bar0 (480): C arrives after the X update; A+B sync at loop top.
//               (extra prologue instance: A+C arrive, B syncs -> X(0) ready)
// Row-wise chained matmuls use an intra-warp smem bounce (STS; __syncwarp;
// LDS.128) — warp c owns row c, so no block barrier is needed. Softmax
// (5-wide, tiny scores -> max subtraction unnecessary) is inline per lane.
// tokemb is staged to smem at entry so the tok->embedding gather is one
// parallel round-trip instead of two chained ones.

#define CTX    5
#define DIM    32
#define NTOK   13
#define HEADS  4
#define HD     8
#define LAYERS 4
#define SCALE  0.17677669529663687f   // 1/sqrt(32)
#define FULL   0xFFFFFFFFu

#define BAR_SYNC(id, n)   asm volatile("bar.sync %0, %1;"   :: "n"(id), "n"(n) : "memory")
#define BAR_ARRIVE(id, n) asm volatile("bar.arrive %0, %1;" :: "n"(id), "n"(n) : "memory")

__global__ __launch_bounds__(480, 1)
void transformer_fused_kernel(
    const int*   __restrict__ toks,
    const float* __restrict__ pos,
    const float* __restrict__ tokemb,
    const float* __restrict__ gWq,
    const float* __restrict__ gWk,
    const float* __restrict__ gWv,
    const float* __restrict__ gWp,
    const float* __restrict__ gbp,
    const float* __restrict__ gW1,
    const float* __restrict__ gb1,
    const float* __restrict__ gW2,
    const float* __restrict__ gb2,
    const float* __restrict__ gWu,
    const float* __restrict__ gbu,
    float*       __restrict__ out)
{
    __shared__ __align__(16) float Xs  [CTX * DIM];
    __shared__ __align__(16) float Qs  [CTX * DIM];   // Q, then Ycat bounce
    __shared__ __align__(16) float Ks  [CTX * DIM];
    __shared__ __align__(16) float Vs  [CTX * DIM];
    __shared__ __align__(16) float Yps [CTX * DIM];
    __shared__ __align__(16) float Hs  [CTX * DIM];   // H bounce (group C)
    __shared__ __align__(16) float temb[NTOK * DIM];  // staged tok embeddings
    __shared__ int toks_s[CTX];

    const int tid = threadIdx.x;
    const int g   = tid / 160;        // 0=A, 1=B, 2=C (warp-aligned)
    const int r   = tid - g * 160;    // 0..159
    const int c   = r >> 5;           // context row (warp-uniform)
    const int d   = r & 31;           // feature column (lane)

    float w0[DIM];    // A: Wq   B: Wk        C: W1
    float w1r[DIM];   // A: Wp   B: Wv -> Wu  C: W2
    float b0 = 0.f;   // A: bp   B: bu(end)   C: b1
    float b1v = 0.f;  //                      C: b2

    // ---- Prologue: stage toks/temb, prefetch layer-0 weights (parallel) ----
    if (tid < CTX) toks_s[tid] = toks[tid];
    float posv = 0.f;
    if (g == 0) {
        posv = pos[r];
        #pragma unroll
        for (int i = 0; i < DIM; ++i) {
            w0[i]  = gWq[i * DIM + d];
            w1r[i] = gWp[i * DIM + d];
        }
        b0 = gbp[d];
    } else if (g == 1) {
        #pragma unroll
        for (int i = 0; i < DIM; ++i) {
            w0[i]  = gWk[i * DIM + d];
            w1r[i] = gWv[i * DIM + d];
        }
    } else {
        if (r < (NTOK * DIM / 4))     // 104 float4: whole embedding table
            ((float4*)temb)[r] = ((const float4*)tokemb)[r];
        #pragma unroll
        for (int i = 0; i < DIM; ++i) {
            w0[i]  = gW1[i * DIM + d];
            w1r[i] = gW2[i * DIM + d];
        }
        b0  = gb1[d];
        b1v = gb2[d];
    }
    __syncthreads();                  // toks_s + temb visible

    // ---- Embedding (A), then prologue bar0 instance: A,C arrive; B syncs ----
    if (g == 0) {
        Xs[r] = temb[toks_s[c] * DIM + d] + posv;
        __syncwarp();                 // warp c produced row c
        BAR_ARRIVE(0, 480);
    } else if (g == 2) {
        BAR_ARRIVE(0, 480);
    }

    #pragma unroll 1
    for (int l = 0; l < LAYERS; ++l) {
        const int ln = l + 1;

        if (g == 0) {
            // ===== Phase 1 (A): Q = X @ Wq -> Qs =====
            if (l > 0) BAR_SYNC(0, 480);           // wait for X(l)
            {
                const float4* xr = (const float4*)(Xs + c * DIM);
                float a0 = 0.f, a1 = 0.f, a2 = 0.f, a3 = 0.f;
                #pragma unroll
                for (int i = 0; i < 8; ++i) {
                    const float4 x = xr[i];
                    a0 = fmaf(x.x, w0[4 * i    ], a0);
                    a1 = fmaf(x.y, w0[4 * i + 1], a1);
                    a2 = fmaf(x.z, w0[4 * i + 2], a2);
                    a3 = fmaf(x.w, w0[4 * i + 3], a3);
                }
                Qs[r] = (a0 + a1) + (a2 + a3);
                __syncwarp();
            }
            if (l < LAYERS - 1) {                  // hidden in wait-for-B slack
                #pragma unroll
                for (int i = 0; i < DIM; ++i)
                    w0[i] = gWq[ln * DIM * DIM + i * DIM + d];
            }
            BAR_SYNC(1, 320);                      // wait for K,V

            // ===== Phase 2 (A): attention inline + Yproj (smem bounce) =====
            {
                const int h    = d >> 3;
                const int base = h * HD;
                const float4 qa = *(const float4*)(Qs + c * DIM + base);
                const float4 qb = *(const float4*)(Qs + c * DIM + base + 4);
                float e[CTX];
                #pragma unroll
                for (int k = 0; k < CTX; ++k) {
                    if (k <= c) {
                        const float4 ka = *(const float4*)(Ks + k * DIM + base);
                        const float4 kb = *(const float4*)(Ks + k * DIM + base + 4);
                        float s0 = qa.x * ka.x + qa.z * ka.z;
                        float s1 = qa.y * ka.y + qa.w * ka.w;
                        s0 += qb.x * kb.x + qb.z * kb.z;
                        s1 += qb.y * kb.y + qb.w * kb.w;
                        e[k] = __expf((s0 + s1) * SCALE);
                    } else {
                        e[k] = 0.f;
                    }
                }
                const float inv =
                    __fdividef(1.f, (e[0] + e[1]) + (e[2] + e[3]) + e[4]);
                float y = e[0] * Vs[0 * DIM + d];
                y = fmaf(e[1], Vs[1 * DIM + d], y);
                y = fmaf(e[2], Vs[2 * DIM + d], y);
                y = fmaf(e[3], Vs[3 * DIM + d], y);
                y = fmaf(e[4], Vs[4 * DIM + d], y);
                y *= inv;                               // Ycat[c][d]

                // intra-warp bounce: row c lives in warp c
                Qs[r] = y;
                __syncwarp();
                const float4* yr = (const float4*)(Qs + c * DIM);
                float p0 = b0, p1 = 0.f, p2 = 0.f, p3 = 0.f;
                #pragma unroll
                for (int i = 0; i < 8; ++i) {
                    const float4 x = yr[i];
                    p0 = fmaf(x.x, w1r[4 * i    ], p0);
                    p1 = fmaf(x.y, w1r[4 * i + 1], p1);
                    p2 = fmaf(x.z, w1r[4 * i + 2], p2);
                    p3 = fmaf(x.w, w1r[4 * i + 3], p3);
                }
                Yps[r] = (p0 + p1) + (p2 + p3);
            }
            BAR_ARRIVE(2, 320);                    // release C immediately
            if (l < LAYERS - 1) {                  // prefetch OFF critical path
                #pragma unroll
                for (int i = 0; i < DIM; ++i)
                    w1r[i] = gWp[ln * DIM * DIM + i * DIM + d];
                b0 = gbp[ln * DIM + d];
            }
        } else if (g == 1) {
            // ===== Phase 1 (B): K,V = X @ {Wk,Wv} -> Ks,Vs =====
            BAR_SYNC(0, 480);                      // wait for X(l)
            {
                const float4* xr = (const float4*)(Xs + c * DIM);
                float k0 = 0.f, k1 = 0.f, k2 = 0.f, k3 = 0.f;
                float v0 = 0.f, v1 = 0.f, v2 = 0.f, v3 = 0.f;
                #pragma unroll
                for (int i = 0; i < 8; ++i) {
                    const float4 x = xr[i];
                    k0 = fmaf(x.x, w0[4 * i    ], k0);
                    k1 = fmaf(x.y, w0[4 * i + 1], k1);
                    k2 = fmaf(x.z, w0[4 * i + 2], k2);
                    k3 = fmaf(x.w, w0[4 * i + 3], k3);
                    v0 = fmaf(x.x, w1r[4 * i    ], v0);
                    v1 = fmaf(x.y, w1r[4 * i + 1], v1);
                    v2 = fmaf(x.z, w1r[4 * i + 2], v2);
                    v3 = fmaf(x.w, w1r[4 * i + 3], v3);
                }
                Ks[r] = (k0 + k1) + (k2 + k3);
                Vs[r] = (v0 + v1) + (v2 + v3);
            }
            BAR_ARRIVE(1, 320);                    // release A immediately
            if (l < LAYERS - 1) {                  // prefetch OFF critical path
                #pragma unroll
                for (int i = 0; i < DIM; ++i) {
                    w0[i]  = gWk[ln * DIM * DIM + i * DIM + d];
                    w1r[i] = gWv[ln * DIM * DIM + i * DIM + d];
                }
            } else if (r < CTX * NTOK) {           // last layer: Wu + bu
                const int t = r % NTOK;
                #pragma unroll
                for (int i = 0; i < DIM; ++i)
                    w1r[i] = gWu[i * NTOK + t];
                b0 = gbu[t];
            }
        } else {
            // ===== Phase 3 (C): H=relu(Yp@W1+b1); Y=H@W2+b2; X update =====
            BAR_SYNC(2, 320);                      // wait for Yps
            {
                const float4* xr = (const float4*)(Yps + c * DIM);
                float a0 = b0, a1 = 0.f, a2 = 0.f, a3 = 0.f;
                #pragma unroll
                for (int i = 0; i < 8; ++i) {
                    const float4 x = xr[i];
                    a0 = fmaf(x.x, w0[4 * i    ], a0);
                    a1 = fmaf(x.y, w0[4 * i + 1], a1);
                    a2 = fmaf(x.z, w0[4 * i + 2], a2);
                    a3 = fmaf(x.w, w0[4 * i + 3], a3);
                }
                const float hval = fmaxf((a0 + a1) + (a2 + a3), 0.f);

                // intra-warp bounce: row c lives in warp c
                Hs[r] = hval;
                __syncwarp();
                const float4* hr = (const float4*)(Hs + c * DIM);
                float y0 = b1v, y1 = 0.f, y2 = 0.f, y3 = 0.f;
                #pragma unroll
                for (int i = 0; i < 8; ++i) {
                    const float4 x = hr[i];
                    y0 = fmaf(x.x, w1r[4 * i    ], y0);
                    y1 = fmaf(x.y, w1r[4 * i + 1], y1);
                    y2 = fmaf(x.z, w1r[4 * i + 2], y2);
                    y3 = fmaf(x.w, w1r[4 * i + 3], y3);
                }
                // sole reader+writer of Xs[r] here: no hazard
                Xs[r] += ((y0 + y1) + (y2 + y3)) + Yps[r];
            }
            BAR_ARRIVE(0, 480);                    // release A,B immediately
            if (l < LAYERS - 1) {                  // prefetch OFF critical path
                #pragma unroll
                for (int i = 0; i < DIM; ++i) {
                    w0[i]  = gW1[ln * DIM * DIM + i * DIM + d];
                    w1r[i] = gW2[ln * DIM * DIM + i * DIM + d];
                }
                b0  = gb1[ln * DIM + d];
                b1v = gb2[ln * DIM + d];
            }
        }
    }

    // ---- Final X barrier, then epilogue (B, Wu in regs) ----
    if (g < 2) {
        BAR_SYNC(0, 480);
        if (g == 1 && r < CTX * NTOK) {
            const int cc = r / NTOK;
            const float4* xr = (const float4*)(Xs + cc * DIM);
            float y0 = b0, y1 = 0.f, y2 = 0.f, y3 = 0.f;
            #pragma unroll
            for (int i = 0; i < 8; ++i) {
                const float4 x = xr[i];
                y0 = fmaf(x.x, w1r[4 * i    ], y0);
                y1 = fmaf(x.y, w1r[4 * i + 1], y1);
                y2 = fmaf(x.z, w1r[4 * i + 2], y2);
                y3 = fmaf(x.w, w1r[4 * i + 3], y3);
            }
            out[r] = (y0 + y1) + (y2 + y3);
        }
    }
}

extern "C" void kernel_launch(void* const* d_in, const int* in_sizes, int n_in,
                              void* d_out, int out_size) {
    (void)in_sizes; (void)n_in; (void)out_size;
    const int*   toks   = (const int*)  d_in[0];
    const float* pos    = (const float*)d_in[1];
    const float* tokemb = (const float*)d_in[2];
    const float* Wq     = (const float*)d_in[3];
    const float* Wk     = (const float*)d_in[4];
    const float* Wv     = (const float*)d_in[5];
    const float* Wp     = (const float*)d_in[6];
    const float* bp     = (const float*)d_in[7];
    const float* W1     = (const float*)d_in[8];
    const float* b1     = (const float*)d_in[9];
    const float* W2     = (const float*)d_in[10];
    const float* b2     = (const float*)d_in[11];
    const float* Wu     = (const float*)d_in[12];
    const float* bu     = (const float*)d_in[13];
    float* out = (float*)d_out;

    transformer_fused_kernel<<<1, 480>>>(toks, pos, tokemb, Wq, Wk, Wv, Wp, bp,
                                         W1, b1, W2, b2, Wu, bu, out);
}